// round 17
// baseline (speedup 1.0000x reference)
#include <cuda_runtime.h>
#include <cstdint>

#define SEQ    2048
#define BATCH  4096
#define IN     4
#define HID    3
#define UNR    32                 // timesteps per pipeline stage
#define STAGES 3                  // smem ring depth -> 48 KB static
#define NGRP   (SEQ / UNR)        // 64 groups

// ---- cp.async ----
__device__ __forceinline__ void cp_async16(void* smem_dst, const void* gmem_src) {
    uint32_t s;
    asm("{ .reg .u64 t; cvta.to.shared.u64 t, %1; cvt.u32.u64 %0, t; }"
        : "=r"(s) : "l"(smem_dst));
    asm volatile("cp.async.ca.shared.global [%0], [%1], 16;"
                 :: "r"(s), "l"(gmem_src) : "memory");
}
__device__ __forceinline__ void cp_async_commit() {
    asm volatile("cp.async.commit_group;" ::: "memory");
}
template <int N>
__device__ __forceinline__ void cp_async_wait() {
    asm volatile("cp.async.wait_group %0;" :: "n"(N) : "memory");
}

__global__ void __launch_bounds__(32, 1)
rnn_relu_kernel(const float* __restrict__ x,      // [SEQ, BATCH, 4]
                const float* __restrict__ h0,     // [1, BATCH, 3]
                const float* __restrict__ W_ih,   // [3, 4]
                const float* __restrict__ W_hh,   // [3, 3]
                const float* __restrict__ b_ih,   // [3]
                const float* __restrict__ b_hh,   // [3]
                float* __restrict__ out)
{
    // One warp per block; each thread owns one batch chain. Sync-free.
    // Parity-split batch mapping: block 2i covers even batches of [64i,64i+64),
    // block 2i+1 the odd ones -> every lane's 12-byte output row admits a
    // uniform STG.64 + STG.32 pair (2 stores/iter instead of 3).
    __shared__ float4 xs[STAGES][UNR][32];   // 48 KB

    const int lane = threadIdx.x;
    const int par  = blockIdx.x & 1;                    // 0: even b, 1: odd b
    const int b    = (blockIdx.x >> 1) * 64 + 2 * lane + par;

    // All-scalar weights (R16): zero per-iter movs, 16-cyc serial chain.
    float wih[HID][IN];
    float whh[HID][HID];
    float bias[HID];
#pragma unroll
    for (int j = 0; j < HID; j++) {
#pragma unroll
        for (int i = 0; i < IN; i++) wih[j][i] = W_ih[j * IN + i];
#pragma unroll
        for (int i = 0; i < HID; i++) whh[j][i] = W_hh[j * HID + i];
        bias[j] = b_ih[j] + b_hh[j];
    }

    float ha = h0[b * HID + 0];
    float hb = h0[b * HID + 1];
    float hc = h0[b * HID + 2];

    const float4* __restrict__ xv = (const float4*)x;  // [SEQ][BATCH]
    float* __restrict__ outs  = out;
    float* __restrict__ hlast = out + (size_t)SEQ * BATCH * HID;

    // Prime STAGES-1 = 2 stages (64 timesteps of lookahead).
#pragma unroll
    for (int s = 0; s < STAGES - 1; s++) {
#pragma unroll
        for (int k = 0; k < UNR; k++)
            cp_async16(&xs[s][k][lane], &xv[(size_t)(s * UNR + k) * BATCH + b]);
        cp_async_commit();
    }

    // Rolling stage counters (no %3): group g lives in stage g mod 3.
    int stage = 0;
    int fill  = STAGES - 1;

    for (int g = 0; g < NGRP; g++) {
        cp_async_wait<STAGES - 2>();   // group g complete (self-written smem)

        const int t0 = g * UNR;
#pragma unroll
        for (int k = 0; k < UNR; k++) {
            const float4 xt = xs[stage][k][lane];

            // Input projection (independent of h -> off the serial chain).
            float p0 = fmaf(wih[0][0], xt.x, bias[0]);
            float p1 = fmaf(wih[1][0], xt.x, bias[1]);
            float p2 = fmaf(wih[2][0], xt.x, bias[2]);
            p0 = fmaf(wih[0][1], xt.y, p0);
            p1 = fmaf(wih[1][1], xt.y, p1);
            p2 = fmaf(wih[2][1], xt.y, p2);
            p0 = fmaf(wih[0][2], xt.z, p0);
            p1 = fmaf(wih[1][2], xt.z, p1);
            p2 = fmaf(wih[2][2], xt.z, p2);
            p0 = fmaf(wih[0][3], xt.w, p0);
            p1 = fmaf(wih[1][3], xt.w, p1);
            p2 = fmaf(wih[2][3], xt.w, p2);

            // Recurrence: serial chain = 3 FFMA + FMNMX = 16 cyc, no movs.
            float a0 = fmaf(whh[0][0], ha, p0);
            float a1 = fmaf(whh[1][0], ha, p1);
            float a2 = fmaf(whh[2][0], ha, p2);
            a0 = fmaf(whh[0][1], hb, a0);
            a1 = fmaf(whh[1][1], hb, a1);
            a2 = fmaf(whh[2][1], hb, a2);
            a0 = fmaf(whh[0][2], hc, a0);
            a1 = fmaf(whh[1][2], hc, a1);
            a2 = fmaf(whh[2][2], hc, a2);

            ha = fmaxf(a0, 0.0f);
            hb = fmaxf(a1, 0.0f);
            hc = fmaxf(a2, 0.0f);

            // Parity-uniform 2-store write of (ha,hb,hc), 12 bytes.
            // even b: byte(o)   = 12b     ≡ 0 (mod 8) -> f2 @ o,  f1 @ o+2
            // odd  b: byte(o+1) = 12b + 4 ≡ 0 (mod 8) -> f1 @ o,  f2 @ o+1
            const size_t o = ((size_t)(t0 + k) * BATCH + b) * HID;
            if (par == 0) {   // uniform per block -> no divergence
                __stcs((float2*)(outs + o), make_float2(ha, hb));
                __stcs(outs + o + 2, hc);
            } else {
                __stcs(outs + o, ha);
                __stcs((float2*)(outs + o + 1), make_float2(hb, hc));
            }
        }

        // Refill stage `fill` with group g + STAGES - 1.
        const int gnext = g + STAGES - 1;
        if (gnext < NGRP) {
#pragma unroll
            for (int k = 0; k < UNR; k++)
                cp_async16(&xs[fill][k][lane],
                           &xv[(size_t)(gnext * UNR + k) * BATCH + b]);
        }
        cp_async_commit();  // uniform group accounting on the tail

        stage = (stage == STAGES - 1) ? 0 : stage + 1;
        fill  = (fill  == STAGES - 1) ? 0 : fill  + 1;
    }

    hlast[b * HID + 0] = ha;
    hlast[b * HID + 1] = hb;
    hlast[b * HID + 2] = hc;
}

extern "C" void kernel_launch(void* const* d_in, const int* in_sizes, int n_in,
                              void* d_out, int out_size)
{
    const float* x    = (const float*)d_in[0];
    const float* h0   = (const float*)d_in[1];
    const float* W_ih = (const float*)d_in[2];
    const float* W_hh = (const float*)d_in[3];
    const float* b_ih = (const float*)d_in[4];
    const float* b_hh = (const float*)d_in[5];
    float* out = (float*)d_out;

    rnn_relu_kernel<<<BATCH / 32, 32>>>(x, h0, W_ih, W_hh, b_ih, b_hh, out);
}